// round 1
// baseline (speedup 1.0000x reference)
#include <cuda_runtime.h>
#include <math.h>

#define NB 8
#define S 2048
#define E 512
#define H 8
#define D 64
#define P 16
#define SK (S + P)   /* 2064 */

// ---------------- device scratch (static, no allocations) ----------------
static __device__ float g_qp[(size_t)NB * H * S * D];        // 33.5 MB
static __device__ float g_kp[(size_t)NB * H * SK * D];       // 33.8 MB
static __device__ float g_vp[(size_t)NB * H * SK * D];       // 33.8 MB
static __device__ float g_energy[(size_t)NB * H * S * SK];   // 1.08 GB
static __device__ float g_att[(size_t)NB * S * E];           // 33.5 MB

// =====================================================================
// K1: per-head projection  y[n,h,s,:] = W @ x[n,s,h,:]   (torch x @ W^T)
// grid: (32 s-tiles, 64 nh), 256 threads, 64x64 tile
// =====================================================================
__global__ __launch_bounds__(256) void proj_kernel(const float* __restrict__ x,
                                                   const float* __restrict__ w,
                                                   int target) {
    float* y;
    int yrows;
    if (target == 0)      { y = g_qp; yrows = S;  }
    else if (target == 1) { y = g_kp; yrows = SK; }
    else                  { y = g_vp; yrows = SK; }

    int stile = blockIdx.x;
    int nh    = blockIdx.y;
    int n = nh >> 3, h = nh & 7;

    __shared__ float Xs[64][65];
    __shared__ float Ws[64][65];

    int tid = threadIdx.x;
    {
        int c = (tid & 15) * 4;
        #pragma unroll
        for (int p = 0; p < 4; ++p) {
            int r = (tid >> 4) + p * 16;
            float4 wv = *(const float4*)&w[r * 64 + c];
            Ws[r][c] = wv.x; Ws[r][c + 1] = wv.y; Ws[r][c + 2] = wv.z; Ws[r][c + 3] = wv.w;
            const float* xp = x + (size_t)(n * S + stile * 64 + r) * E + h * 64 + c;
            float4 xv = *(const float4*)xp;
            Xs[r][c] = xv.x; Xs[r][c + 1] = xv.y; Xs[r][c + 2] = xv.z; Xs[r][c + 3] = xv.w;
        }
    }
    __syncthreads();

    int tx = tid & 15, ty = tid >> 4;
    float acc[4][4] = {};
    #pragma unroll
    for (int kk = 0; kk < 64; ++kk) {
        float a[4], b[4];
        #pragma unroll
        for (int i = 0; i < 4; ++i) a[i] = Xs[ty + 16 * i][kk];
        #pragma unroll
        for (int j = 0; j < 4; ++j) b[j] = Ws[tx + 16 * j][kk];
        #pragma unroll
        for (int i = 0; i < 4; ++i)
            #pragma unroll
            for (int j = 0; j < 4; ++j)
                acc[i][j] += a[i] * b[j];
    }

    #pragma unroll
    for (int i = 0; i < 4; ++i) {
        int row = stile * 64 + ty + 16 * i;
        float* yp = y + ((size_t)nh * yrows + row) * 64;
        #pragma unroll
        for (int j = 0; j < 4; ++j)
            yp[tx + 16 * j] = acc[i][j];
    }
}

// =====================================================================
// K1b: copy persistent tokens (appended AFTER projection, per reference)
// =====================================================================
__global__ void persist_kernel(const float* __restrict__ pk,
                               const float* __restrict__ pv) {
    int idx = blockIdx.x * 256 + threadIdx.x;
    if (idx >= NB * H * P * D) return;
    int d = idx & 63;
    int t = idx >> 6;
    int p = t & 15; t >>= 4;
    int h = t & 7;
    int n = t >> 3;
    size_t dst = ((size_t)(n * H + h) * SK + S + p) * D + d;
    size_t src = ((size_t)p * H + h) * D + d;
    g_kp[dst] = pk[src];
    g_vp[dst] = pv[src];
}

// =====================================================================
// K2: energy[n,h,q,k] = qp[n,h,q,:] . kp[n,h,k,:]
// per (n,h): M=2048, N=2064, K=64.  128x128 tile, 8x8 strided microtile.
// grid: (17 ntiles, 16 mtiles, 64 batches)
// =====================================================================
__global__ __launch_bounds__(256) void energy_kernel() {
    int nt = blockIdx.x;
    int mt = blockIdx.y;
    int b  = blockIdx.z;

    __shared__ float As[128][33];
    __shared__ float Bs[128][33];

    const float* A = g_qp + (size_t)b * S * D + (size_t)mt * 128 * D;
    const float* B = g_kp + (size_t)b * SK * D + (size_t)nt * 128 * D;
    int n0 = nt * 128;
    int tid = threadIdx.x;
    int tx = tid & 15, ty = tid >> 4;

    float acc[8][8] = {};

    #pragma unroll
    for (int kc = 0; kc < 64; kc += 32) {
        __syncthreads();
        int c = (tid & 7) * 4;
        #pragma unroll
        for (int p = 0; p < 4; ++p) {
            int r = (tid >> 3) + p * 32;
            float4 av = *(const float4*)&A[(size_t)r * 64 + kc + c];
            As[r][c] = av.x; As[r][c + 1] = av.y; As[r][c + 2] = av.z; As[r][c + 3] = av.w;
            float4 bv = make_float4(0.f, 0.f, 0.f, 0.f);
            if (n0 + r < SK) bv = *(const float4*)&B[(size_t)r * 64 + kc + c];
            Bs[r][c] = bv.x; Bs[r][c + 1] = bv.y; Bs[r][c + 2] = bv.z; Bs[r][c + 3] = bv.w;
        }
        __syncthreads();
        #pragma unroll
        for (int kk = 0; kk < 32; ++kk) {
            float a[8], bb[8];
            #pragma unroll
            for (int i = 0; i < 8; ++i) a[i] = As[ty + 16 * i][kk];
            #pragma unroll
            for (int j = 0; j < 8; ++j) bb[j] = Bs[tx + 16 * j][kk];
            #pragma unroll
            for (int i = 0; i < 8; ++i)
                #pragma unroll
                for (int j = 0; j < 8; ++j)
                    acc[i][j] += a[i] * bb[j];
        }
    }

    size_t rowbase = (size_t)b * S + (size_t)mt * 128;
    #pragma unroll
    for (int i = 0; i < 8; ++i) {
        size_t rb = (rowbase + ty + 16 * i) * SK + n0;
        #pragma unroll
        for (int j = 0; j < 8; ++j) {
            int cc = tx + 16 * j;
            if (n0 + cc < SK) g_energy[rb + cc] = acc[i][j];
        }
    }
}

// =====================================================================
// K3: alibi + pre talking-heads + mask + softmax + post talking-heads.
// One CTA per (n,q). 256 threads, each owns up to 9 k-positions x 8 heads.
// In-place on g_energy.
// =====================================================================
__global__ __launch_bounds__(256) void softmax_kernel(const int* __restrict__ mask,
                                                      const float* __restrict__ pre,
                                                      const float* __restrict__ post) {
    const float inv_sqrt_e = 0.044194173824159216f;  // 1/sqrt(512)
    int nq = blockIdx.x;
    int n = nq >> 11, q = nq & 2047;
    int tid = threadIdx.x;
    int lane = tid & 31, wid = tid >> 5;

    __shared__ float s_pre[64], s_post[64], s_red[64];
    if (tid < 64) s_pre[tid] = pre[tid];
    else if (tid < 128) s_post[tid - 64] = post[tid - 64];
    __syncthreads();

    const int KPT = 9;  // ceil(2064/256)
    float l[8][KPT];
    const int* mrow = mask + ((size_t)n * S + q) * S;
    size_t hstride = (size_t)S * SK;
    size_t b0 = ((size_t)(n * H) * S + q) * SK;

    float slope[8];
    #pragma unroll
    for (int h = 0; h < 8; ++h) slope[h] = exp2f(-(float)(h + 1));

    #pragma unroll
    for (int it = 0; it < KPT; ++it) {
        int k = tid + it * 256;
        if (k < SK) {
            float e[8];
            #pragma unroll
            for (int j = 0; j < 8; ++j) e[j] = g_energy[b0 + (size_t)j * hstride + k];
            if (k < S) {
                float dist = fabsf((float)(q - k));
                #pragma unroll
                for (int j = 0; j < 8; ++j) e[j] -= dist * slope[j];
            }
            int mk = (k < S) ? mrow[k] : 1;
            #pragma unroll
            for (int h = 0; h < 8; ++h) {
                float m = 0.f;
                #pragma unroll
                for (int j = 0; j < 8; ++j) m += s_pre[h * 8 + j] * e[j];
                l[h][it] = (mk == 0 ? -1e4f : m) * inv_sqrt_e;
            }
        } else {
            #pragma unroll
            for (int h = 0; h < 8; ++h) l[h][it] = -INFINITY;
        }
    }

    // per-head block max
    float mx[8], inv[8];
    #pragma unroll
    for (int h = 0; h < 8; ++h) {
        float v = -INFINITY;
        #pragma unroll
        for (int it = 0; it < KPT; ++it) v = fmaxf(v, l[h][it]);
        #pragma unroll
        for (int off = 16; off > 0; off >>= 1)
            v = fmaxf(v, __shfl_xor_sync(0xffffffffu, v, off));
        if (lane == 0) s_red[h * 8 + wid] = v;
    }
    __syncthreads();
    #pragma unroll
    for (int h = 0; h < 8; ++h) {
        float v = -INFINITY;
        #pragma unroll
        for (int w = 0; w < 8; ++w) v = fmaxf(v, s_red[h * 8 + w]);
        mx[h] = v;
    }
    __syncthreads();

    // exp + per-head block sum
    #pragma unroll
    for (int h = 0; h < 8; ++h) {
        float v = 0.f;
        #pragma unroll
        for (int it = 0; it < KPT; ++it) {
            float ev = __expf(l[h][it] - mx[h]);
            l[h][it] = ev;
            v += ev;
        }
        #pragma unroll
        for (int off = 16; off > 0; off >>= 1)
            v += __shfl_xor_sync(0xffffffffu, v, off);
        if (lane == 0) s_red[h * 8 + wid] = v;
    }
    __syncthreads();
    #pragma unroll
    for (int h = 0; h < 8; ++h) {
        float v = 0.f;
        #pragma unroll
        for (int w = 0; w < 8; ++w) v += s_red[h * 8 + w];
        inv[h] = 1.f / v;
    }

    // normalize, post-mix, write back
    #pragma unroll
    for (int it = 0; it < KPT; ++it) {
        int k = tid + it * 256;
        if (k < SK) {
            float p[8];
            #pragma unroll
            for (int j = 0; j < 8; ++j) p[j] = l[j][it] * inv[j];
            #pragma unroll
            for (int h = 0; h < 8; ++h) {
                float a = 0.f;
                #pragma unroll
                for (int j = 0; j < 8; ++j) a += s_post[h * 8 + j] * p[j];
                g_energy[b0 + (size_t)h * hstride + k] = a;
            }
        }
    }
}

// =====================================================================
// K4: out_h[n,h,q,:] = attn[n,h,q,:] @ vp[n,h,:,:]
// per (n,h): M=2048, N=64, K=2064.  256x64 tile, strided 8x8 microtile.
// writes directly in [n,q,e] layout (heads concatenated).
// grid: (1, 8 mtiles, 64 batches)
// =====================================================================
__global__ __launch_bounds__(256) void av_kernel() {
    int mt = blockIdx.y;
    int b  = blockIdx.z;

    __shared__ float As[256][33];
    __shared__ float Bs[32][65];

    const float* Ap = g_energy + ((size_t)b * S + (size_t)mt * 256) * SK;
    const float* Bp = g_vp + (size_t)b * SK * D;

    int tid = threadIdx.x;
    int tx = tid & 7, ty = tid >> 3;
    float acc[8][8] = {};

    for (int kc = 0; kc < SK; kc += 32) {
        __syncthreads();
        {
            int c = (tid & 7) * 4;
            #pragma unroll
            for (int p = 0; p < 8; ++p) {
                int r = (tid >> 3) + p * 32;
                float4 av = make_float4(0.f, 0.f, 0.f, 0.f);
                if (kc + c < SK) av = *(const float4*)&Ap[(size_t)r * SK + kc + c];
                As[r][c] = av.x; As[r][c + 1] = av.y; As[r][c + 2] = av.z; As[r][c + 3] = av.w;
            }
            int c2 = (tid & 15) * 4;
            #pragma unroll
            for (int p = 0; p < 2; ++p) {
                int r = (tid >> 4) + p * 16;
                float4 bv = make_float4(0.f, 0.f, 0.f, 0.f);
                if (kc + r < SK) bv = *(const float4*)&Bp[(size_t)(kc + r) * D + c2];
                Bs[r][c2] = bv.x; Bs[r][c2 + 1] = bv.y; Bs[r][c2 + 2] = bv.z; Bs[r][c2 + 3] = bv.w;
            }
        }
        __syncthreads();
        #pragma unroll
        for (int kk = 0; kk < 32; ++kk) {
            float a[8], bb[8];
            #pragma unroll
            for (int i = 0; i < 8; ++i) a[i] = As[ty + 32 * i][kk];
            #pragma unroll
            for (int j = 0; j < 8; ++j) bb[j] = Bs[kk][tx + 8 * j];
            #pragma unroll
            for (int i = 0; i < 8; ++i)
                #pragma unroll
                for (int j = 0; j < 8; ++j)
                    acc[i][j] += a[i] * bb[j];
        }
    }

    int n = b >> 3, h = b & 7;
    #pragma unroll
    for (int i = 0; i < 8; ++i) {
        int qrow = mt * 256 + ty + 32 * i;
        float* op = g_att + ((size_t)n * S + qrow) * E + h * D;
        #pragma unroll
        for (int j = 0; j < 8; ++j)
            op[tx + 8 * j] = acc[i][j];
    }
}

// =====================================================================
// K5: out = g_att @ Wo^T + bo.   M=16384, N=512, K=512.
// grid: (4 ntiles, 128 mtiles)
// =====================================================================
__global__ __launch_bounds__(256) void outproj_kernel(const float* __restrict__ Wo,
                                                      const float* __restrict__ bo,
                                                      float* __restrict__ out) {
    int nt = blockIdx.x;
    int mt = blockIdx.y;

    __shared__ float As[128][33];
    __shared__ float Bs[128][33];

    const float* Ap = g_att + (size_t)mt * 128 * E;
    const float* Bp = Wo + (size_t)nt * 128 * E;

    int tid = threadIdx.x;
    int tx = tid & 15, ty = tid >> 4;
    float acc[8][8] = {};

    for (int kc = 0; kc < E; kc += 32) {
        __syncthreads();
        int c = (tid & 7) * 4;
        #pragma unroll
        for (int p = 0; p < 4; ++p) {
            int r = (tid >> 3) + p * 32;
            float4 av = *(const float4*)&Ap[(size_t)r * E + kc + c];
            As[r][c] = av.x; As[r][c + 1] = av.y; As[r][c + 2] = av.z; As[r][c + 3] = av.w;
            float4 bv = *(const float4*)&Bp[(size_t)r * E + kc + c];
            Bs[r][c] = bv.x; Bs[r][c + 1] = bv.y; Bs[r][c + 2] = bv.z; Bs[r][c + 3] = bv.w;
        }
        __syncthreads();
        #pragma unroll
        for (int kk = 0; kk < 32; ++kk) {
            float a[8], bb[8];
            #pragma unroll
            for (int i = 0; i < 8; ++i) a[i] = As[ty + 16 * i][kk];
            #pragma unroll
            for (int j = 0; j < 8; ++j) bb[j] = Bs[tx + 16 * j][kk];
            #pragma unroll
            for (int i = 0; i < 8; ++i)
                #pragma unroll
                for (int j = 0; j < 8; ++j)
                    acc[i][j] += a[i] * bb[j];
        }
    }

    #pragma unroll
    for (int i = 0; i < 8; ++i) {
        int row = mt * 128 + ty + 16 * i;
        #pragma unroll
        for (int j = 0; j < 8; ++j) {
            int col = nt * 128 + tx + 16 * j;
            out[(size_t)row * E + col] = acc[i][j] + bo[col];
        }
    }
}

// =====================================================================
extern "C" void kernel_launch(void* const* d_in, const int* in_sizes, int n_in,
                              void* d_out, int out_size) {
    const float* values  = (const float*)d_in[0];
    const float* keys    = (const float*)d_in[1];
    const float* queries = (const float*)d_in[2];
    const int*   mask    = (const int*)d_in[3];
    const float* Wv      = (const float*)d_in[4];
    const float* Wk      = (const float*)d_in[5];
    const float* Wq      = (const float*)d_in[6];
    const float* Wo      = (const float*)d_in[7];
    const float* bo      = (const float*)d_in[8];
    const float* pre_th  = (const float*)d_in[9];
    const float* post_th = (const float*)d_in[10];
    const float* pk      = (const float*)d_in[11];
    const float* pv      = (const float*)d_in[12];
    float* out = (float*)d_out;

    proj_kernel<<<dim3(32, 64), 256>>>(queries, Wq, 0);
    proj_kernel<<<dim3(32, 64), 256>>>(keys,    Wk, 1);
    proj_kernel<<<dim3(32, 64), 256>>>(values,  Wv, 2);
    persist_kernel<<<dim3(256), 256>>>(pk, pv);
    energy_kernel<<<dim3(17, 16, 64), 256>>>();
    softmax_kernel<<<dim3(16384), 256>>>(mask, pre_th, post_th);
    av_kernel<<<dim3(1, 8, 64), 256>>>();
    outproj_kernel<<<dim3(4, 128), 256>>>(Wo, bo, out);
}

// round 5
// speedup vs baseline: 1.9122x; 1.9122x over previous
#include <cuda_runtime.h>
#include <math.h>
#include <stdint.h>

#define NB 8
#define S 2048
#define E 512
#define H 8
#define D 64
#define P 16
#define SK (S + P)   /* 2064 */
#define EL 68        /* smem row stride in floats; 68 % 32 == 4 -> conflict-free frags */

// ---------------- device scratch (static, no allocations) ----------------
static __device__ float g_qp[(size_t)NB * H * S * D];        // tf32-rounded
static __device__ float g_kp[(size_t)NB * H * SK * D];       // tf32-rounded
static __device__ float g_vt[(size_t)NB * H * D * SK];       // V transposed [b][d][k], tf32-rounded
static __device__ float g_energy[(size_t)NB * H * S * SK];   // 1.08 GB
static __device__ float g_att[(size_t)NB * S * E];

// =====================================================================
// helpers
// =====================================================================
__device__ __forceinline__ uint32_t smem_u32(const void* p) {
    uint32_t a;
    asm("{ .reg .u64 t; cvta.to.shared.u64 t, %1; cvt.u32.u64 %0, t; }" : "=r"(a) : "l"(p));
    return a;
}
__device__ __forceinline__ float to_tf32(float x) {
    uint32_t r;
    asm("cvt.rna.tf32.f32 %0, %1;" : "=r"(r) : "f"(x));
    return __uint_as_float(r);
}
__device__ __forceinline__ void mma_tf32(float c[4], const float a[4], const float b[2]) {
    asm volatile(
        "mma.sync.aligned.m16n8k8.row.col.f32.tf32.tf32.f32 "
        "{%0,%1,%2,%3}, {%4,%5,%6,%7}, {%8,%9}, {%0,%1,%2,%3};"
        : "+f"(c[0]), "+f"(c[1]), "+f"(c[2]), "+f"(c[3])
        : "r"(__float_as_uint(a[0])), "r"(__float_as_uint(a[1])),
          "r"(__float_as_uint(a[2])), "r"(__float_as_uint(a[3])),
          "r"(__float_as_uint(b[0])), "r"(__float_as_uint(b[1])));
}
__device__ __forceinline__ void cp_async16(uint32_t dst, const void* src, int srcsize) {
    asm volatile("cp.async.cg.shared.global [%0], [%1], 16, %2;"
                 :: "r"(dst), "l"(src), "r"(srcsize) : "memory");
}
__device__ __forceinline__ void cp_commit() {
    asm volatile("cp.async.commit_group;" ::: "memory");
}

// =====================================================================
// K1: per-head projection (tf32-rounded output; V written transposed)
// =====================================================================
__global__ __launch_bounds__(256) void proj_kernel(const float* __restrict__ x,
                                                   const float* __restrict__ w,
                                                   int target) {
    int stile = blockIdx.x;
    int nh    = blockIdx.y;
    int n = nh >> 3, h = nh & 7;

    __shared__ float Xs[64][65];
    __shared__ float Ws[64][65];

    int tid = threadIdx.x;
    {
        int c = (tid & 15) * 4;
        #pragma unroll
        for (int p = 0; p < 4; ++p) {
            int r = (tid >> 4) + p * 16;
            float4 wv = *(const float4*)&w[r * 64 + c];
            Ws[r][c] = wv.x; Ws[r][c + 1] = wv.y; Ws[r][c + 2] = wv.z; Ws[r][c + 3] = wv.w;
            const float* xp = x + (size_t)(n * S + stile * 64 + r) * E + h * 64 + c;
            float4 xv = *(const float4*)xp;
            Xs[r][c] = xv.x; Xs[r][c + 1] = xv.y; Xs[r][c + 2] = xv.z; Xs[r][c + 3] = xv.w;
        }
    }
    __syncthreads();

    int tx = tid & 15, ty = tid >> 4;
    float acc[4][4] = {};
    #pragma unroll
    for (int kk = 0; kk < 64; ++kk) {
        float a[4], b[4];
        #pragma unroll
        for (int i = 0; i < 4; ++i) a[i] = Xs[ty + 16 * i][kk];
        #pragma unroll
        for (int j = 0; j < 4; ++j) b[j] = Ws[tx + 16 * j][kk];
        #pragma unroll
        for (int i = 0; i < 4; ++i)
            #pragma unroll
            for (int j = 0; j < 4; ++j)
                acc[i][j] += a[i] * b[j];
    }

    if (target != 2) {
        float* y = (target == 0) ? g_qp : g_kp;
        int yrows = (target == 0) ? S : SK;
        #pragma unroll
        for (int i = 0; i < 4; ++i) {
            int row = stile * 64 + ty + 16 * i;
            float* yp = y + ((size_t)nh * yrows + row) * 64;
            #pragma unroll
            for (int j = 0; j < 4; ++j)
                yp[tx + 16 * j] = to_tf32(acc[i][j]);
        }
    } else {
        // transpose in smem, write g_vt[b][d][k] coalesced
        __syncthreads();
        #pragma unroll
        for (int i = 0; i < 4; ++i)
            #pragma unroll
            for (int j = 0; j < 4; ++j)
                Xs[tx + 16 * j][ty + 16 * i] = to_tf32(acc[i][j]);
        __syncthreads();
        // scalar smem reads (row stride 65 is odd -> no vector LDS), vector global store
        int d = tid >> 2, c4 = (tid & 3) * 16;
        float* yp = g_vt + ((size_t)nh * 64 + d) * SK + stile * 64 + c4;
        #pragma unroll
        for (int wv = 0; wv < 4; ++wv) {
            float4 v = make_float4(Xs[d][c4 + wv * 4 + 0], Xs[d][c4 + wv * 4 + 1],
                                   Xs[d][c4 + wv * 4 + 2], Xs[d][c4 + wv * 4 + 3]);
            *(float4*)(yp + wv * 4) = v;
        }
    }
}

// =====================================================================
// K1b: persistent tokens (tf32-rounded; V transposed)
// =====================================================================
__global__ void persist_kernel(const float* __restrict__ pk,
                               const float* __restrict__ pv) {
    int idx = blockIdx.x * 256 + threadIdx.x;
    if (idx >= NB * H * P * D) return;
    int d = idx & 63;
    int t = idx >> 6;
    int p = t & 15; t >>= 4;
    int h = t & 7;
    int n = t >> 3;
    int b = n * H + h;
    size_t src = ((size_t)p * H + h) * D + d;
    g_kp[((size_t)b * SK + S + p) * D + d] = to_tf32(pk[src]);
    g_vt[((size_t)b * 64 + d) * SK + S + p] = to_tf32(pv[src]);
}

// =====================================================================
// K2: energy via mma.sync tf32.  CTA tile 128x128, K=64.
// 8 warps = 2(m) x 4(n), warp tile 64x32.  grid: (17, 16, 64), 256 thr.
// =====================================================================
#define ESMEM_BYTES (2 * 128 * EL * 4)
__global__ __launch_bounds__(256) void energy_mma() {
    extern __shared__ float sm[];
    float* As = sm;               // 128 x EL
    float* Bs = sm + 128 * EL;    // 128 x EL

    int tid = threadIdx.x, wid = tid >> 5, lane = tid & 31;
    int nt = blockIdx.x, mt = blockIdx.y, b = blockIdx.z;
    int n0 = nt * 128;

    const float* A = g_qp + ((size_t)b * S + (size_t)mt * 128) * 64;
    const float* Bsrc = g_kp + (size_t)b * SK * 64;

    #pragma unroll
    for (int p = 0; p < 8; ++p) {
        int idx = tid + p * 256;
        int r = idx >> 4, c4 = (idx & 15) * 4;
        *(float4*)&As[r * EL + c4] = *(const float4*)(A + (size_t)r * 64 + c4);
        float4 v = make_float4(0.f, 0.f, 0.f, 0.f);
        if (n0 + r < SK) v = *(const float4*)(Bsrc + (size_t)(n0 + r) * 64 + c4);
        *(float4*)&Bs[r * EL + c4] = v;
    }
    __syncthreads();

    int warpM = (wid & 1) * 64, warpN = (wid >> 1) * 32;
    int r0 = lane >> 2, c0 = lane & 3;
    float acc[4][4][4] = {};

    #pragma unroll
    for (int ks = 0; ks < 8; ++ks) {
        int k0 = ks * 8;
        float a[4][4];
        #pragma unroll
        for (int mf = 0; mf < 4; ++mf) {
            int base = (warpM + mf * 16 + r0) * EL + k0 + c0;
            a[mf][0] = As[base];
            a[mf][1] = As[base + 8 * EL];
            a[mf][2] = As[base + 4];
            a[mf][3] = As[base + 8 * EL + 4];
        }
        float bb[4][2];
        #pragma unroll
        for (int nf = 0; nf < 4; ++nf) {
            int base = (warpN + nf * 8 + r0) * EL + k0 + c0;
            bb[nf][0] = Bs[base];
            bb[nf][1] = Bs[base + 4];
        }
        #pragma unroll
        for (int mf = 0; mf < 4; ++mf)
            #pragma unroll
            for (int nf = 0; nf < 4; ++nf)
                mma_tf32(acc[mf][nf], a[mf], bb[nf]);
    }

    size_t grow = (size_t)b * S + (size_t)mt * 128;
    #pragma unroll
    for (int mf = 0; mf < 4; ++mf) {
        int rr = warpM + mf * 16 + r0;
        #pragma unroll
        for (int nf = 0; nf < 4; ++nf) {
            int cc = n0 + warpN + nf * 8 + c0 * 2;
            if (cc < SK) {
                float* pp = g_energy + (grow + rr) * SK + cc;
                *(float2*)pp = make_float2(acc[mf][nf][0], acc[mf][nf][1]);
                *(float2*)(pp + 8 * SK) = make_float2(acc[mf][nf][2], acc[mf][nf][3]);
            }
        }
    }
}

// =====================================================================
// K3: alibi + pre talking-heads + mask + softmax + post talking-heads.
// =====================================================================
__global__ __launch_bounds__(256) void softmax_kernel(const int* __restrict__ mask,
                                                      const float* __restrict__ pre,
                                                      const float* __restrict__ post) {
    const float inv_sqrt_e = 0.044194173824159216f;
    int nq = blockIdx.x;
    int n = nq >> 11, q = nq & 2047;
    int tid = threadIdx.x;
    int lane = tid & 31, wid = tid >> 5;

    __shared__ float s_pre[64], s_post[64], s_red[64];
    if (tid < 64) s_pre[tid] = pre[tid];
    else if (tid < 128) s_post[tid - 64] = post[tid - 64];
    __syncthreads();

    const int KPT = 9;
    float l[8][KPT];
    const int* mrow = mask + ((size_t)n * S + q) * S;
    size_t hstride = (size_t)S * SK;
    size_t b0 = ((size_t)(n * H) * S + q) * SK;

    float slope[8];
    #pragma unroll
    for (int h = 0; h < 8; ++h) slope[h] = exp2f(-(float)(h + 1));

    #pragma unroll
    for (int it = 0; it < KPT; ++it) {
        int k = tid + it * 256;
        if (k < SK) {
            float e[8];
            #pragma unroll
            for (int j = 0; j < 8; ++j) e[j] = g_energy[b0 + (size_t)j * hstride + k];
            if (k < S) {
                float dist = fabsf((float)(q - k));
                #pragma unroll
                for (int j = 0; j < 8; ++j) e[j] -= dist * slope[j];
            }
            int mk = (k < S) ? mrow[k] : 1;
            #pragma unroll
            for (int h = 0; h < 8; ++h) {
                float m = 0.f;
                #pragma unroll
                for (int j = 0; j < 8; ++j) m += s_pre[h * 8 + j] * e[j];
                l[h][it] = (mk == 0 ? -1e4f : m) * inv_sqrt_e;
            }
        } else {
            #pragma unroll
            for (int h = 0; h < 8; ++h) l[h][it] = -INFINITY;
        }
    }

    float mx[8], inv[8];
    #pragma unroll
    for (int h = 0; h < 8; ++h) {
        float v = -INFINITY;
        #pragma unroll
        for (int it = 0; it < KPT; ++it) v = fmaxf(v, l[h][it]);
        #pragma unroll
        for (int off = 16; off > 0; off >>= 1)
            v = fmaxf(v, __shfl_xor_sync(0xffffffffu, v, off));
        if (lane == 0) s_red[h * 8 + wid] = v;
    }
    __syncthreads();
    #pragma unroll
    for (int h = 0; h < 8; ++h) {
        float v = -INFINITY;
        #pragma unroll
        for (int w = 0; w < 8; ++w) v = fmaxf(v, s_red[h * 8 + w]);
        mx[h] = v;
    }
    __syncthreads();

    #pragma unroll
    for (int h = 0; h < 8; ++h) {
        float v = 0.f;
        #pragma unroll
        for (int it = 0; it < KPT; ++it) {
            float ev = __expf(l[h][it] - mx[h]);
            l[h][it] = ev;
            v += ev;
        }
        #pragma unroll
        for (int off = 16; off > 0; off >>= 1)
            v += __shfl_xor_sync(0xffffffffu, v, off);
        if (lane == 0) s_red[h * 8 + wid] = v;
    }
    __syncthreads();
    #pragma unroll
    for (int h = 0; h < 8; ++h) {
        float v = 0.f;
        #pragma unroll
        for (int w = 0; w < 8; ++w) v += s_red[h * 8 + w];
        inv[h] = 1.f / v;
    }

    #pragma unroll
    for (int it = 0; it < KPT; ++it) {
        int k = tid + it * 256;
        if (k < SK) {
            float p[8];
            #pragma unroll
            for (int j = 0; j < 8; ++j) p[j] = l[j][it] * inv[j];
            #pragma unroll
            for (int h = 0; h < 8; ++h) {
                float a = 0.f;
                #pragma unroll
                for (int j = 0; j < 8; ++j) a += s_post[h * 8 + j] * p[j];
                g_energy[b0 + (size_t)h * hstride + k] = a;
            }
        }
    }
}

// =====================================================================
// K4: AV via mma.sync tf32.  CTA tile 128x64, K=2064 in 33 chunks of 64,
// 2-stage cp.async pipeline.  8 warps = 4(m) x 2(n), warp 32x32.
// grid: (16 mtiles, 64 batches), 256 threads.
// =====================================================================
#define AV_ASZ (128 * EL)
#define AV_BSZ (64 * EL)
#define AVSMEM_BYTES (2 * (AV_ASZ + AV_BSZ) * 4)
#define NCHUNK 33
__global__ __launch_bounds__(256) void av_mma() {
    extern __shared__ float sm[];
    int tid = threadIdx.x, wid = tid >> 5, lane = tid & 31;
    int mt = blockIdx.x, b = blockIdx.y;

    const float* Ap = g_energy + ((size_t)b * S + (size_t)mt * 128) * SK;
    const float* Vt = g_vt + (size_t)b * 64 * SK;

    uint32_t sbase = smem_u32(sm);

    auto load_chunk = [&](int ci, int buf) {
        int kc = ci * 64;
        uint32_t abase = sbase + (uint32_t)(buf * (AV_ASZ + AV_BSZ)) * 4;
        uint32_t bbase = abase + (uint32_t)AV_ASZ * 4;
        #pragma unroll
        for (int p = 0; p < 8; ++p) {
            int g = tid + p * 256;
            int r = g >> 4, kq = (g & 15) * 4;
            int ss = (kc + kq < SK) ? 16 : 0;
            cp_async16(abase + (uint32_t)(r * EL + kq) * 4,
                       Ap + (size_t)r * SK + kc + kq, ss);
        }
        #pragma unroll
        for (int p = 0; p < 4; ++p) {
            int g = tid + p * 256;
            int d = g >> 4, kq = (g & 15) * 4;
            int ss = (kc + kq < SK) ? 16 : 0;
            cp_async16(bbase + (uint32_t)(d * EL + kq) * 4,
                       Vt + (size_t)d * SK + kc + kq, ss);
        }
        cp_commit();
    };

    load_chunk(0, 0);

    int warpM = (wid & 3) * 32, warpN = (wid >> 2) * 32;
    int r0 = lane >> 2, c0 = lane & 3;
    float acc[2][4][4] = {};

    for (int ci = 0; ci < NCHUNK; ++ci) {
        int buf = ci & 1;
        if (ci + 1 < NCHUNK) {
            load_chunk(ci + 1, buf ^ 1);
            asm volatile("cp.async.wait_group 1;" ::: "memory");
        } else {
            asm volatile("cp.async.wait_group 0;" ::: "memory");
        }
        __syncthreads();

        const float* As = sm + buf * (AV_ASZ + AV_BSZ);
        const float* Bs = As + AV_ASZ;

        #pragma unroll
        for (int ks = 0; ks < 8; ++ks) {
            int k0 = ks * 8;
            float a[2][4];
            #pragma unroll
            for (int mf = 0; mf < 2; ++mf) {
                int base = (warpM + mf * 16 + r0) * EL + k0 + c0;
                a[mf][0] = to_tf32(As[base]);
                a[mf][1] = to_tf32(As[base + 8 * EL]);
                a[mf][2] = to_tf32(As[base + 4]);
                a[mf][3] = to_tf32(As[base + 8 * EL + 4]);
            }
            float bb[4][2];
            #pragma unroll
            for (int nf = 0; nf < 4; ++nf) {
                int base = (warpN + nf * 8 + r0) * EL + k0 + c0;
                bb[nf][0] = Bs[base];
                bb[nf][1] = Bs[base + 4];
            }
            #pragma unroll
            for (int mf = 0; mf < 2; ++mf)
                #pragma unroll
                for (int nf = 0; nf < 4; ++nf)
                    mma_tf32(acc[mf][nf], a[mf], bb[nf]);
        }
        __syncthreads();
    }

    int n = b >> 3, h = b & 7;
    #pragma unroll
    for (int mf = 0; mf < 2; ++mf) {
        int row = mt * 128 + warpM + mf * 16 + r0;
        #pragma unroll
        for (int nf = 0; nf < 4; ++nf) {
            int col = warpN + nf * 8 + c0 * 2;
            float* pp = g_att + ((size_t)n * S + row) * E + h * 64 + col;
            *(float2*)pp = make_float2(acc[mf][nf][0], acc[mf][nf][1]);
            *(float2*)(pp + 8 * E) = make_float2(acc[mf][nf][2], acc[mf][nf][3]);
        }
    }
}

// =====================================================================
// K5: out = g_att @ Wo^T + bo.
// =====================================================================
__global__ __launch_bounds__(256) void outproj_kernel(const float* __restrict__ Wo,
                                                      const float* __restrict__ bo,
                                                      float* __restrict__ out) {
    int nt = blockIdx.x;
    int mt = blockIdx.y;

    __shared__ float As[128][33];
    __shared__ float Bs[128][33];

    const float* Ap = g_att + (size_t)mt * 128 * E;
    const float* Bp = Wo + (size_t)nt * 128 * E;

    int tid = threadIdx.x;
    int tx = tid & 15, ty = tid >> 4;
    float acc[8][8] = {};

    for (int kc = 0; kc < E; kc += 32) {
        __syncthreads();
        int c = (tid & 7) * 4;
        #pragma unroll
        for (int p = 0; p < 4; ++p) {
            int r = (tid >> 3) + p * 32;
            float4 av = *(const float4*)&Ap[(size_t)r * E + kc + c];
            As[r][c] = av.x; As[r][c + 1] = av.y; As[r][c + 2] = av.z; As[r][c + 3] = av.w;
            float4 bv = *(const float4*)&Bp[(size_t)r * E + kc + c];
            Bs[r][c] = bv.x; Bs[r][c + 1] = bv.y; Bs[r][c + 2] = bv.z; Bs[r][c + 3] = bv.w;
        }
        __syncthreads();
        #pragma unroll
        for (int kk = 0; kk < 32; ++kk) {
            float a[8], bb[8];
            #pragma unroll
            for (int i = 0; i < 8; ++i) a[i] = As[ty + 16 * i][kk];
            #pragma unroll
            for (int j = 0; j < 8; ++j) bb[j] = Bs[tx + 16 * j][kk];
            #pragma unroll
            for (int i = 0; i < 8; ++i)
                #pragma unroll
                for (int j = 0; j < 8; ++j)
                    acc[i][j] += a[i] * bb[j];
        }
    }

    #pragma unroll
    for (int i = 0; i < 8; ++i) {
        int row = mt * 128 + ty + 16 * i;
        #pragma unroll
        for (int j = 0; j < 8; ++j) {
            int col = nt * 128 + tx + 16 * j;
            out[(size_t)row * E + col] = acc[i][j] + bo[col];
        }
    }
}

// =====================================================================
extern "C" void kernel_launch(void* const* d_in, const int* in_sizes, int n_in,
                              void* d_out, int out_size) {
    const float* values  = (const float*)d_in[0];
    const float* keys    = (const float*)d_in[1];
    const float* queries = (const float*)d_in[2];
    const int*   mask    = (const int*)d_in[3];
    const float* Wv      = (const float*)d_in[4];
    const float* Wk      = (const float*)d_in[5];
    const float* Wq      = (const float*)d_in[6];
    const float* Wo      = (const float*)d_in[7];
    const float* bo      = (const float*)d_in[8];
    const float* pre_th  = (const float*)d_in[9];
    const float* post_th = (const float*)d_in[10];
    const float* pk      = (const float*)d_in[11];
    const float* pv      = (const float*)d_in[12];
    float* out = (float*)d_out;

    cudaFuncSetAttribute(energy_mma, cudaFuncAttributeMaxDynamicSharedMemorySize, ESMEM_BYTES);
    cudaFuncSetAttribute(av_mma,     cudaFuncAttributeMaxDynamicSharedMemorySize, AVSMEM_BYTES);

    proj_kernel<<<dim3(32, 64), 256>>>(queries, Wq, 0);
    proj_kernel<<<dim3(32, 64), 256>>>(keys,    Wk, 1);
    proj_kernel<<<dim3(32, 64), 256>>>(values,  Wv, 2);
    persist_kernel<<<dim3(256), 256>>>(pk, pv);
    energy_mma<<<dim3(17, 16, 64), 256, ESMEM_BYTES>>>();
    softmax_kernel<<<dim3(16384), 256>>>(mask, pre_th, post_th);
    av_mma<<<dim3(16, 64), 256, AVSMEM_BYTES>>>();
    outproj_kernel<<<dim3(4, 128), 256>>>(Wo, bo, out);
}

// round 6
// speedup vs baseline: 2.7457x; 1.4358x over previous
#include <cuda_runtime.h>
#include <cuda_fp16.h>
#include <math.h>
#include <stdint.h>

#define NB 8
#define S 2048
#define E 512
#define H 8
#define D 64
#define P 16
#define SK (S + P)   /* 2064 */
#define HL 72        /* smem row stride in halfs; 144B -> 36-word stride, conflict-free */

// ---------------- device scratch (static, no allocations) ----------------
static __device__ __half g_qp[(size_t)NB * H * S * D];
static __device__ __half g_kp[(size_t)NB * H * SK * D];
static __device__ __half g_vt[(size_t)NB * H * D * SK];      // V transposed [b][d][k]
static __device__ __half g_energy[(size_t)NB * H * S * SK];  // 540 MB, reused for probs
static __device__ __half g_att[(size_t)NB * S * E];
static __device__ __half g_wo[(size_t)E * E];

// =====================================================================
// helpers
// =====================================================================
__device__ __forceinline__ uint32_t smem_u32(const void* p) {
    uint32_t a;
    asm("{ .reg .u64 t; cvta.to.shared.u64 t, %1; cvt.u32.u64 %0, t; }" : "=r"(a) : "l"(p));
    return a;
}
__device__ __forceinline__ void mma_f16(float c[4], const uint32_t a[4], const uint32_t b[2]) {
    asm volatile(
        "mma.sync.aligned.m16n8k16.row.col.f32.f16.f16.f32 "
        "{%0,%1,%2,%3}, {%4,%5,%6,%7}, {%8,%9}, {%0,%1,%2,%3};"
        : "+f"(c[0]), "+f"(c[1]), "+f"(c[2]), "+f"(c[3])
        : "r"(a[0]), "r"(a[1]), "r"(a[2]), "r"(a[3]), "r"(b[0]), "r"(b[1]));
}
__device__ __forceinline__ void cp_async16(uint32_t dst, const void* src, int srcsize) {
    asm volatile("cp.async.cg.shared.global [%0], [%1], 16, %2;"
                 :: "r"(dst), "l"(src), "r"(srcsize) : "memory");
}
__device__ __forceinline__ void cp_commit() {
    asm volatile("cp.async.commit_group;" ::: "memory");
}

// =====================================================================
// K1: per-head projection -> fp16 outputs (V written transposed)
// =====================================================================
__global__ __launch_bounds__(256) void proj_kernel(const float* __restrict__ x,
                                                   const float* __restrict__ w,
                                                   int target) {
    int stile = blockIdx.x;
    int nh    = blockIdx.y;
    int n = nh >> 3, h = nh & 7;

    __shared__ float Xs[64][65];
    __shared__ float Ws[64][65];

    int tid = threadIdx.x;
    {
        int c = (tid & 15) * 4;
        #pragma unroll
        for (int p = 0; p < 4; ++p) {
            int r = (tid >> 4) + p * 16;
            float4 wv = *(const float4*)&w[r * 64 + c];
            Ws[r][c] = wv.x; Ws[r][c + 1] = wv.y; Ws[r][c + 2] = wv.z; Ws[r][c + 3] = wv.w;
            const float* xp = x + (size_t)(n * S + stile * 64 + r) * E + h * 64 + c;
            float4 xv = *(const float4*)xp;
            Xs[r][c] = xv.x; Xs[r][c + 1] = xv.y; Xs[r][c + 2] = xv.z; Xs[r][c + 3] = xv.w;
        }
    }
    __syncthreads();

    int tx = tid & 15, ty = tid >> 4;
    float acc[4][4] = {};
    #pragma unroll
    for (int kk = 0; kk < 64; ++kk) {
        float a[4], b[4];
        #pragma unroll
        for (int i = 0; i < 4; ++i) a[i] = Xs[ty + 16 * i][kk];
        #pragma unroll
        for (int j = 0; j < 4; ++j) b[j] = Ws[tx + 16 * j][kk];
        #pragma unroll
        for (int i = 0; i < 4; ++i)
            #pragma unroll
            for (int j = 0; j < 4; ++j)
                acc[i][j] += a[i] * b[j];
    }

    if (target != 2) {
        __half* y = (target == 0) ? g_qp : g_kp;
        int yrows = (target == 0) ? S : SK;
        #pragma unroll
        for (int i = 0; i < 4; ++i) {
            int row = stile * 64 + ty + 16 * i;
            __half* yp = y + ((size_t)nh * yrows + row) * 64;
            #pragma unroll
            for (int j = 0; j < 4; ++j)
                yp[tx + 16 * j] = __float2half_rn(acc[i][j]);
        }
    } else {
        // transpose in smem, write g_vt[b][d][k]
        __syncthreads();
        #pragma unroll
        for (int i = 0; i < 4; ++i)
            #pragma unroll
            for (int j = 0; j < 4; ++j)
                Xs[tx + 16 * j][ty + 16 * i] = acc[i][j];
        __syncthreads();
        int d = tid >> 2, c4 = (tid & 3) * 16;
        __half* yp = g_vt + ((size_t)nh * 64 + d) * SK + stile * 64 + c4;
        #pragma unroll
        for (int i = 0; i < 8; ++i)
            *(__half2*)(yp + 2 * i) = __floats2half2_rn(Xs[d][c4 + 2 * i], Xs[d][c4 + 2 * i + 1]);
    }
}

// =====================================================================
// K1b: persistent tokens (fp16; V transposed)
// =====================================================================
__global__ void persist_kernel(const float* __restrict__ pk,
                               const float* __restrict__ pv) {
    int idx = blockIdx.x * 256 + threadIdx.x;
    if (idx >= NB * H * P * D) return;
    int d = idx & 63;
    int t = idx >> 6;
    int p = t & 15; t >>= 4;
    int h = t & 7;
    int n = t >> 3;
    int b = n * H + h;
    size_t src = ((size_t)p * H + h) * D + d;
    g_kp[((size_t)b * SK + S + p) * D + d] = __float2half_rn(pk[src]);
    g_vt[((size_t)b * 64 + d) * SK + S + p] = __float2half_rn(pv[src]);
}

// =====================================================================
// K1c: Wo -> fp16
// =====================================================================
__global__ void convert_wo(const float* __restrict__ Wo) {
    int idx = blockIdx.x * 256 + threadIdx.x;
    g_wo[idx] = __float2half_rn(Wo[idx]);
}

// =====================================================================
// K2: energy via mma.sync fp16.  CTA 128x128, K=64 (4 k16-steps).
// 8 warps = 2(m) x 4(n), warp 64x32.  grid: (17, 16, 64), 256 thr.
// =====================================================================
__global__ __launch_bounds__(256) void energy_mma() {
    __shared__ __half As[128 * HL];
    __shared__ __half Bs[128 * HL];

    int tid = threadIdx.x, wid = tid >> 5, lane = tid & 31;
    int nt = blockIdx.x, mt = blockIdx.y, b = blockIdx.z;
    int n0 = nt * 128;

    const __half* A = g_qp + ((size_t)b * S + (size_t)mt * 128) * 64;
    const __half* Bsrc = g_kp + (size_t)b * SK * 64;

    #pragma unroll
    for (int p = 0; p < 4; ++p) {
        int idx = tid + p * 256;
        int r = idx >> 3, c8 = (idx & 7) * 8;
        *(float4*)&As[r * HL + c8] = *(const float4*)(A + (size_t)r * 64 + c8);
        float4 v = make_float4(0.f, 0.f, 0.f, 0.f);
        if (n0 + r < SK) v = *(const float4*)(Bsrc + (size_t)(n0 + r) * 64 + c8);
        *(float4*)&Bs[r * HL + c8] = v;
    }
    __syncthreads();

    int warpM = (wid & 1) * 64, warpN = (wid >> 1) * 32;
    int r0 = lane >> 2, c0 = lane & 3;
    float acc[4][4][4] = {};

    #pragma unroll
    for (int ks = 0; ks < 4; ++ks) {
        int k0 = ks * 16;
        uint32_t a[4][4];
        #pragma unroll
        for (int mf = 0; mf < 4; ++mf) {
            int base = (warpM + mf * 16 + r0) * HL + k0 + 2 * c0;
            a[mf][0] = *(const uint32_t*)&As[base];
            a[mf][1] = *(const uint32_t*)&As[base + 8 * HL];
            a[mf][2] = *(const uint32_t*)&As[base + 8];
            a[mf][3] = *(const uint32_t*)&As[base + 8 * HL + 8];
        }
        uint32_t bb[4][2];
        #pragma unroll
        for (int nf = 0; nf < 4; ++nf) {
            int base = (warpN + nf * 8 + r0) * HL + k0 + 2 * c0;
            bb[nf][0] = *(const uint32_t*)&Bs[base];
            bb[nf][1] = *(const uint32_t*)&Bs[base + 8];
        }
        #pragma unroll
        for (int mf = 0; mf < 4; ++mf)
            #pragma unroll
            for (int nf = 0; nf < 4; ++nf)
                mma_f16(acc[mf][nf], a[mf], bb[nf]);
    }

    size_t grow = (size_t)b * S + (size_t)mt * 128;
    #pragma unroll
    for (int mf = 0; mf < 4; ++mf) {
        int rr = warpM + mf * 16 + r0;
        #pragma unroll
        for (int nf = 0; nf < 4; ++nf) {
            int cc = n0 + warpN + nf * 8 + 2 * c0;
            if (cc < SK) {
                __half* pp = g_energy + (grow + rr) * SK + cc;
                *(__half2*)pp = __floats2half2_rn(acc[mf][nf][0], acc[mf][nf][1]);
                *(__half2*)(pp + (size_t)8 * SK) = __floats2half2_rn(acc[mf][nf][2], acc[mf][nf][3]);
            }
        }
    }
}

// =====================================================================
// K3: alibi + pre talking-heads + mask + softmax + post talking-heads.
// fp16 in/out, fp32 math.  One CTA per (n,q).
// =====================================================================
__global__ __launch_bounds__(256) void softmax_kernel(const int* __restrict__ mask,
                                                      const float* __restrict__ pre,
                                                      const float* __restrict__ post) {
    const float inv_sqrt_e = 0.044194173824159216f;
    int nq = blockIdx.x;
    int n = nq >> 11, q = nq & 2047;
    int tid = threadIdx.x;
    int lane = tid & 31, wid = tid >> 5;

    __shared__ float s_pre[64], s_post[64], s_red[64];
    if (tid < 64) s_pre[tid] = pre[tid];
    else if (tid < 128) s_post[tid - 64] = post[tid - 64];
    __syncthreads();

    const int KPT = 9;
    float l[8][KPT];
    const int* mrow = mask + ((size_t)n * S + q) * S;
    size_t hstride = (size_t)S * SK;
    size_t b0 = ((size_t)(n * H) * S + q) * SK;

    float slope[8];
    #pragma unroll
    for (int h = 0; h < 8; ++h) slope[h] = exp2f(-(float)(h + 1));

    #pragma unroll
    for (int it = 0; it < KPT; ++it) {
        int k = tid + it * 256;
        if (k < SK) {
            float e[8];
            #pragma unroll
            for (int j = 0; j < 8; ++j) e[j] = __half2float(g_energy[b0 + (size_t)j * hstride + k]);
            if (k < S) {
                float dist = fabsf((float)(q - k));
                #pragma unroll
                for (int j = 0; j < 8; ++j) e[j] -= dist * slope[j];
            }
            int mk = (k < S) ? mrow[k] : 1;
            #pragma unroll
            for (int h = 0; h < 8; ++h) {
                float m = 0.f;
                #pragma unroll
                for (int j = 0; j < 8; ++j) m += s_pre[h * 8 + j] * e[j];
                l[h][it] = (mk == 0 ? -1e4f : m) * inv_sqrt_e;
            }
        } else {
            #pragma unroll
            for (int h = 0; h < 8; ++h) l[h][it] = -INFINITY;
        }
    }

    float mx[8], inv[8];
    #pragma unroll
    for (int h = 0; h < 8; ++h) {
        float v = -INFINITY;
        #pragma unroll
        for (int it = 0; it < KPT; ++it) v = fmaxf(v, l[h][it]);
        #pragma unroll
        for (int off = 16; off > 0; off >>= 1)
            v = fmaxf(v, __shfl_xor_sync(0xffffffffu, v, off));
        if (lane == 0) s_red[h * 8 + wid] = v;
    }
    __syncthreads();
    #pragma unroll
    for (int h = 0; h < 8; ++h) {
        float v = -INFINITY;
        #pragma unroll
        for (int w = 0; w < 8; ++w) v = fmaxf(v, s_red[h * 8 + w]);
        mx[h] = v;
    }
    __syncthreads();

    #pragma unroll
    for (int h = 0; h < 8; ++h) {
        float v = 0.f;
        #pragma unroll
        for (int it = 0; it < KPT; ++it) {
            float ev = __expf(l[h][it] - mx[h]);
            l[h][it] = ev;
            v += ev;
        }
        #pragma unroll
        for (int off = 16; off > 0; off >>= 1)
            v += __shfl_xor_sync(0xffffffffu, v, off);
        if (lane == 0) s_red[h * 8 + wid] = v;
    }
    __syncthreads();
    #pragma unroll
    for (int h = 0; h < 8; ++h) {
        float v = 0.f;
        #pragma unroll
        for (int w = 0; w < 8; ++w) v += s_red[h * 8 + w];
        inv[h] = 1.f / v;
    }

    #pragma unroll
    for (int it = 0; it < KPT; ++it) {
        int k = tid + it * 256;
        if (k < SK) {
            float p[8];
            #pragma unroll
            for (int j = 0; j < 8; ++j) p[j] = l[j][it] * inv[j];
            #pragma unroll
            for (int h = 0; h < 8; ++h) {
                float a = 0.f;
                #pragma unroll
                for (int j = 0; j < 8; ++j) a += s_post[h * 8 + j] * p[j];
                g_energy[b0 + (size_t)h * hstride + k] = __float2half_rn(a);
            }
        }
    }
}

// =====================================================================
// K4: AV via mma.sync fp16.  CTA 128x64, K=2064 in 33 chunks of 64,
// 2-stage cp.async pipeline.  8 warps = 4(m) x 2(n), warp 32x32.
// grid: (16 mtiles, 64 batches), 256 threads.
// =====================================================================
#define AV_ABYTES (128 * HL * 2)      /* 18432 */
#define AV_BBYTES (64 * HL * 2)       /*  9216 */
#define AV_BUFB   (AV_ABYTES + AV_BBYTES)
#define AVSMEM_BYTES (2 * AV_BUFB)    /* 55296 */
#define NCHUNK 33
__global__ __launch_bounds__(256) void av_mma() {
    extern __shared__ __half smh[];
    int tid = threadIdx.x, wid = tid >> 5, lane = tid & 31;
    int mt = blockIdx.x, b = blockIdx.y;

    const __half* Ap = g_energy + ((size_t)b * S + (size_t)mt * 128) * SK;
    const __half* Vt = g_vt + (size_t)b * 64 * SK;

    uint32_t sbase = smem_u32(smh);

    auto load_chunk = [&](int ci, int buf) {
        int kc = ci * 64;
        uint32_t abase = sbase + (uint32_t)buf * AV_BUFB;
        uint32_t bbase = abase + AV_ABYTES;
        #pragma unroll
        for (int p = 0; p < 4; ++p) {
            int g = tid + p * 256;
            int r = g >> 3, c8 = (g & 7) * 8;
            int ss = (kc + c8 < SK) ? 16 : 0;
            cp_async16(abase + (uint32_t)(r * HL + c8) * 2,
                       Ap + (size_t)r * SK + kc + c8, ss);
        }
        #pragma unroll
        for (int p = 0; p < 2; ++p) {
            int g = tid + p * 256;
            int d = g >> 3, c8 = (g & 7) * 8;
            int ss = (kc + c8 < SK) ? 16 : 0;
            cp_async16(bbase + (uint32_t)(d * HL + c8) * 2,
                       Vt + (size_t)d * SK + kc + c8, ss);
        }
        cp_commit();
    };

    load_chunk(0, 0);

    int warpM = (wid & 3) * 32, warpN = (wid >> 2) * 32;
    int r0 = lane >> 2, c0 = lane & 3;
    float acc[2][4][4] = {};

    for (int ci = 0; ci < NCHUNK; ++ci) {
        int buf = ci & 1;
        if (ci + 1 < NCHUNK) {
            load_chunk(ci + 1, buf ^ 1);
            asm volatile("cp.async.wait_group 1;" ::: "memory");
        } else {
            asm volatile("cp.async.wait_group 0;" ::: "memory");
        }
        __syncthreads();

        const __half* As = smh + (size_t)buf * (AV_BUFB / 2);
        const __half* Bs = As + AV_ABYTES / 2;

        #pragma unroll
        for (int ks = 0; ks < 4; ++ks) {
            int k0 = ks * 16;
            uint32_t a[2][4];
            #pragma unroll
            for (int mf = 0; mf < 2; ++mf) {
                int base = (warpM + mf * 16 + r0) * HL + k0 + 2 * c0;
                a[mf][0] = *(const uint32_t*)&As[base];
                a[mf][1] = *(const uint32_t*)&As[base + 8 * HL];
                a[mf][2] = *(const uint32_t*)&As[base + 8];
                a[mf][3] = *(const uint32_t*)&As[base + 8 * HL + 8];
            }
            uint32_t bb[4][2];
            #pragma unroll
            for (int nf = 0; nf < 4; ++nf) {
                int base = (warpN + nf * 8 + r0) * HL + k0 + 2 * c0;
                bb[nf][0] = *(const uint32_t*)&Bs[base];
                bb[nf][1] = *(const uint32_t*)&Bs[base + 8];
            }
            #pragma unroll
            for (int mf = 0; mf < 2; ++mf)
                #pragma unroll
                for (int nf = 0; nf < 4; ++nf)
                    mma_f16(acc[mf][nf], a[mf], bb[nf]);
        }
        __syncthreads();
    }

    int n = b >> 3, h = b & 7;
    #pragma unroll
    for (int mf = 0; mf < 2; ++mf) {
        int row = mt * 128 + warpM + mf * 16 + r0;
        #pragma unroll
        for (int nf = 0; nf < 4; ++nf) {
            int col = warpN + nf * 8 + 2 * c0;
            __half* pp = g_att + ((size_t)n * S + row) * E + h * 64 + col;
            *(__half2*)pp = __floats2half2_rn(acc[mf][nf][0], acc[mf][nf][1]);
            *(__half2*)(pp + (size_t)8 * E) = __floats2half2_rn(acc[mf][nf][2], acc[mf][nf][3]);
        }
    }
}

// =====================================================================
// K5: out = g_att @ Wo^T + bo via fp16 mma.  CTA 128x128, K=512 (8 chunks).
// grid: (4 nt, 128 mt), 256 threads.
// =====================================================================
__global__ __launch_bounds__(256) void outproj_mma(const float* __restrict__ bo,
                                                   float* __restrict__ out) {
    __shared__ __half As[128 * HL];
    __shared__ __half Bs[128 * HL];

    int tid = threadIdx.x, wid = tid >> 5, lane = tid & 31;
    int nt = blockIdx.x, mt = blockIdx.y;

    const __half* Ap = g_att + (size_t)mt * 128 * E;
    const __half* Bp = g_wo + (size_t)nt * 128 * E;

    int warpM = (wid & 1) * 64, warpN = (wid >> 1) * 32;
    int r0 = lane >> 2, c0 = lane & 3;
    float acc[4][4][4] = {};

    for (int kc = 0; kc < E; kc += 64) {
        __syncthreads();
        #pragma unroll
        for (int p = 0; p < 4; ++p) {
            int idx = tid + p * 256;
            int r = idx >> 3, c8 = (idx & 7) * 8;
            *(float4*)&As[r * HL + c8] = *(const float4*)(Ap + (size_t)r * E + kc + c8);
            *(float4*)&Bs[r * HL + c8] = *(const float4*)(Bp + (size_t)r * E + kc + c8);
        }
        __syncthreads();

        #pragma unroll
        for (int ks = 0; ks < 4; ++ks) {
            int k0 = ks * 16;
            uint32_t a[4][4];
            #pragma unroll
            for (int mf = 0; mf < 4; ++mf) {
                int base = (warpM + mf * 16 + r0) * HL + k0 + 2 * c0;
                a[mf][0] = *(const uint32_t*)&As[base];
                a[mf][1] = *(const uint32_t*)&As[base + 8 * HL];
                a[mf][2] = *(const uint32_t*)&As[base + 8];
                a[mf][3] = *(const uint32_t*)&As[base + 8 * HL + 8];
            }
            uint32_t bb[4][2];
            #pragma unroll
            for (int nf = 0; nf < 4; ++nf) {
                int base = (warpN + nf * 8 + r0) * HL + k0 + 2 * c0;
                bb[nf][0] = *(const uint32_t*)&Bs[base];
                bb[nf][1] = *(const uint32_t*)&Bs[base + 8];
            }
            #pragma unroll
            for (int mf = 0; mf < 4; ++mf)
                #pragma unroll
                for (int nf = 0; nf < 4; ++nf)
                    mma_f16(acc[mf][nf], a[mf], bb[nf]);
        }
    }

    #pragma unroll
    for (int mf = 0; mf < 4; ++mf) {
        int row = mt * 128 + warpM + mf * 16 + r0;
        #pragma unroll
        for (int nf = 0; nf < 4; ++nf) {
            int col = nt * 128 + warpN + nf * 8 + 2 * c0;
            float b0v = bo[col], b1v = bo[col + 1];
            float* pp = out + (size_t)row * E + col;
            pp[0] = acc[mf][nf][0] + b0v;
            pp[1] = acc[mf][nf][1] + b1v;
            pp += (size_t)8 * E;
            pp[0] = acc[mf][nf][2] + b0v;
            pp[1] = acc[mf][nf][3] + b1v;
        }
    }
}

// =====================================================================
extern "C" void kernel_launch(void* const* d_in, const int* in_sizes, int n_in,
                              void* d_out, int out_size) {
    const float* values  = (const float*)d_in[0];
    const float* keys    = (const float*)d_in[1];
    const float* queries = (const float*)d_in[2];
    const int*   mask    = (const int*)d_in[3];
    const float* Wv      = (const float*)d_in[4];
    const float* Wk      = (const float*)d_in[5];
    const float* Wq      = (const float*)d_in[6];
    const float* Wo      = (const float*)d_in[7];
    const float* bo      = (const float*)d_in[8];
    const float* pre_th  = (const float*)d_in[9];
    const float* post_th = (const float*)d_in[10];
    const float* pk      = (const float*)d_in[11];
    const float* pv      = (const float*)d_in[12];
    float* out = (float*)d_out;

    cudaFuncSetAttribute(av_mma, cudaFuncAttributeMaxDynamicSharedMemorySize, AVSMEM_BYTES);

    proj_kernel<<<dim3(32, 64), 256>>>(queries, Wq, 0);
    proj_kernel<<<dim3(32, 64), 256>>>(keys,    Wk, 1);
    proj_kernel<<<dim3(32, 64), 256>>>(values,  Wv, 2);
    persist_kernel<<<dim3(256), 256>>>(pk, pv);
    convert_wo<<<dim3(1024), 256>>>(Wo);
    energy_mma<<<dim3(17, 16, 64), 256>>>();
    softmax_kernel<<<dim3(16384), 256>>>(mask, pre_th, post_th);
    av_mma<<<dim3(16, 64), 256, AVSMEM_BYTES>>>();
    outproj_mma<<<dim3(4, 128), 256>>>(bo, out);
}